// round 15
// baseline (speedup 1.0000x reference)
#include <cuda_runtime.h>
#include <cuda_fp16.h>
#include <cstdint>

#define BB 32
#define NR 36
#define DD 2048
#define CC 4
#define HH 512
#define HF 512
#define NROWS (BB*NR)   // 1152

// Scratch (static device globals)
__device__ __half g_mmh [NROWS*DD];   // mm in f16
__device__ __half g_Lh  [NROWS*HF];   // fl f16
__device__ __half g_Rh  [NROWS*HF];   // fr f16
__device__ __half g_Wt  [DD*HF];      // W_fout^T: [d][k]
__device__ __half g_WffT[1024*DD];    // [h][k] fused (W_fl|W_fr) transposed
__device__ __half g_T   [DD*16];      // coord tensor T[d][p*4+q] * 64
__device__ float  g_Tp  [16][DD*16];  // h-split partials for T
__device__ __half g_A   [288*144*HF]; // materialized pair products (42.3 MB)

// ---------------- helpers ----------------
__device__ __forceinline__ uint32_t sm_u32(const void* p){
    uint32_t a;
    asm("{ .reg .u64 t; cvta.to.shared.u64 t, %1; cvt.u32.u64 %0, t; }" : "=r"(a) : "l"(p));
    return a;
}
__device__ __forceinline__ void mma16816(float c[4], const uint32_t a[4], const uint32_t b0, const uint32_t b1){
    asm volatile("mma.sync.aligned.m16n8k16.row.col.f32.f16.f16.f32 "
                 "{%0,%1,%2,%3}, {%4,%5,%6,%7}, {%8,%9}, {%0,%1,%2,%3};\n"
                 : "+f"(c[0]), "+f"(c[1]), "+f"(c[2]), "+f"(c[3])
                 : "r"(a[0]), "r"(a[1]), "r"(a[2]), "r"(a[3]), "r"(b0), "r"(b1));
}
__device__ __forceinline__ void ldm_x4(uint32_t d[4], uint32_t addr){
    asm volatile("ldmatrix.sync.aligned.m8n8.x4.shared.b16 {%0,%1,%2,%3}, [%4];"
                 : "=r"(d[0]), "=r"(d[1]), "=r"(d[2]), "=r"(d[3]) : "r"(addr));
}
__device__ __forceinline__ void cpa16(uint32_t dst, const void* src){
    asm volatile("cp.async.cg.shared.global [%0], [%1], 16;"
                 :: "r"(dst), "l"(__cvta_generic_to_global(src)) : "memory");
}
__device__ __forceinline__ void cpa_commit(){ asm volatile("cp.async.commit_group;" ::: "memory"); }
__device__ __forceinline__ void cpa_wait0(){ asm volatile("cp.async.wait_group 0;" ::: "memory"); }
__device__ __forceinline__ void cpa_wait1(){ asm volatile("cp.async.wait_group 1;" ::: "memory"); }
__device__ __forceinline__ unsigned f2mono(float v){
    unsigned b = __float_as_uint(v);
    return (b & 0x80000000u) ? ~b : (b | 0x80000000u);
}
__device__ __forceinline__ float mono2f(unsigned u){
    return (u & 0x80000000u) ? __uint_as_float(u ^ 0x80000000u) : __uint_as_float(~u);
}

// ---------------- fused prep kernel ----------------
__global__ __launch_bounds__(256) void prep_all(const float* __restrict__ mm,
                                                const float* __restrict__ Wfout,
                                                const float* __restrict__ Wfl,
                                                const float* __restrict__ Wfr,
                                                const float* __restrict__ Wcl,
                                                const float* __restrict__ Wcr,
                                                const float* __restrict__ Wcout){
    __shared__ float ts[64][33];
    __shared__ float scl[4][32], scr[4][32];
    const int bid = blockIdx.x, tid = threadIdx.x;
    if (bid < 1152){
        int i = bid*256 + tid;
        const float4* s = reinterpret_cast<const float4*>(mm);
        float4 v0 = s[i*2], v1 = s[i*2+1];
        __half2* d = reinterpret_cast<__half2*>(g_mmh) + i*4;
        d[0] = __floats2half2_rn(v0.x, v0.y);
        d[1] = __floats2half2_rn(v0.z, v0.w);
        d[2] = __floats2half2_rn(v1.x, v1.y);
        d[3] = __floats2half2_rn(v1.z, v1.w);
    } else if (bid < 1664){
        int q = bid - 1152;
        int d0 = (q&31)*64, k0 = (q>>5)*32;
#pragma unroll
        for (int r=0;r<8;r++){
            int idx = tid + 256*r;
            int kk = idx>>6, dd = idx&63;
            ts[dd][kk] = Wfout[(size_t)(k0+kk)*DD + d0 + dd];
        }
        __syncthreads();
        __half2* Wt2 = reinterpret_cast<__half2*>(g_Wt);
#pragma unroll
        for (int r=0;r<4;r++){
            int idx = tid + 256*r;
            int dd = idx>>4, kk2 = idx&15;
            Wt2[(size_t)(d0+dd)*(HF/2) + (k0>>1) + kk2] =
                __floats2half2_rn(ts[dd][kk2*2], ts[dd][kk2*2+1]);
        }
    } else if (bid < 2688){
        int q = bid - 1664;
        int h0 = (q&15)*64, k0 = (q>>4)*32;
#pragma unroll
        for (int r=0;r<8;r++){
            int idx = tid + 256*r;
            int kk = idx>>6, hh = idx&63;
            int h = h0 + hh, k = k0 + kk;
            ts[hh][kk] = (h < HH) ? Wfl[(size_t)k*HH + h] : Wfr[(size_t)k*HH + h - HH];
        }
        __syncthreads();
        __half2* W2 = reinterpret_cast<__half2*>(g_WffT);
#pragma unroll
        for (int r=0;r<4;r++){
            int idx = tid + 256*r;
            int hh = idx>>4, kk2 = idx&15;
            W2[(size_t)(h0+hh)*(DD/2) + (k0>>1) + kk2] =
                __floats2half2_rn(ts[hh][kk2*2], ts[hh][kk2*2+1]);
        }
    } else {
        int q = bid - 2688;
        int dblk = q&7, hc = q>>3;
        int hbase = hc*32;
        if (tid < 128){
            int p = tid>>5, hh = tid&31;
            scl[p][hh] = Wcl[p*HH + hbase + hh];
            scr[p][hh] = Wcr[p*HH + hbase + hh];
        }
        __syncthreads();
        int d = dblk*256 + tid;
        float acc[16];
#pragma unroll
        for (int e=0;e<16;e++) acc[e]=0.f;
#pragma unroll
        for (int h0=0; h0<32; h0+=8){
            float wc[8];
#pragma unroll
            for (int u=0;u<8;u++) wc[u] = Wcout[(size_t)(hbase+h0+u)*DD + d];
#pragma unroll
            for (int u=0;u<8;u++){
                int hh = h0+u;
#pragma unroll
                for (int p=0;p<4;p++){
                    float a = scl[p][hh]*wc[u];
#pragma unroll
                    for (int r=0;r<4;r++) acc[p*4+r] = fmaf(a, scr[r][hh], acc[p*4+r]);
                }
            }
        }
#pragma unroll
        for (int e=0;e<16;e++) g_Tp[hc][d*16+e] = acc[e];
    }
}
__global__ void prep_T_final(){
    int i = blockIdx.x*256 + threadIdx.x;       // 32768 total
    float s = 0.f;
#pragma unroll
    for (int p=0;p<16;p++) s += g_Tp[p][i];
    g_T[i] = __float2half(s*64.0f);
}

// ---------------- stage 1 ----------------
#define S1_A0 0
#define S1_A1 5120
#define S1_B0 10240
#define S1_B1 20480

__device__ __forceinline__ void s1_issue(uint32_t smb, int t, int sel, int tid, int m0, int n0){
    uint32_t Ab = smb + (sel ? S1_A1 : S1_A0);
    uint32_t Bb = smb + (sel ? S1_B1 : S1_B0);
    {
        int row = tid>>2, seg = tid&3;
        cpa16(Ab + row*80 + seg*16, (const char*)g_mmh + (size_t)(m0+row)*4096 + t*64 + seg*16);
    }
#pragma unroll
    for (int q=0;q<2;q++){
        int idx = tid + 256*q, row = idx>>2, seg = idx&3;
        cpa16(Bb + row*80 + seg*16, (const char*)g_WffT + (size_t)(n0+row)*4096 + t*64 + seg*16);
    }
    cpa_commit();
}

__global__ __launch_bounds__(256) void stage1_gemm(){
    __shared__ char sm[30720];
    uint32_t smb = sm_u32(sm);
    int tid = threadIdx.x, warp = tid>>5, lane = tid&31;
    int n0 = blockIdx.x*128, m0 = blockIdx.y*64;
    int wm = (warp&1)*32, wn = (warp>>1)*32;
    float acc[2][4][4];
#pragma unroll
    for (int a=0;a<2;a++) for (int b=0;b<4;b++) for (int c=0;c<4;c++) acc[a][b][c]=0.f;

    s1_issue(smb, 0, 0, tid, m0, n0);
    for (int t=0; t<64; t++){
        int sel = t&1;
        if (t<63){ s1_issue(smb, t+1, sel^1, tid, m0, n0); cpa_wait1(); }
        else cpa_wait0();
        __syncthreads();
        uint32_t Ab = smb + (sel ? S1_A1 : S1_A0);
        uint32_t Bb = smb + (sel ? S1_B1 : S1_B0);
#pragma unroll
        for (int ks=0; ks<2; ks++){
            uint32_t a[2][4], bfr[2][4];
#pragma unroll
            for (int mf=0;mf<2;mf++)
                ldm_x4(a[mf], Ab + (uint32_t)(wm+mf*16+(lane&15))*80 + ks*32 + ((lane>>4)<<4));
#pragma unroll
            for (int g=0;g<2;g++)
                ldm_x4(bfr[g], Bb + (uint32_t)(wn+g*16+(lane&15))*80 + ks*32 + ((lane>>4)<<4));
#pragma unroll
            for (int mf=0;mf<2;mf++)
#pragma unroll
                for (int g=0;g<2;g++)
#pragma unroll
                    for (int hi=0;hi<2;hi++)
                        mma16816(acc[mf][g*2+hi], a[mf], bfr[g][hi], bfr[g][hi+2]);
        }
        __syncthreads();
    }
#pragma unroll
    for (int mf=0;mf<2;mf++)
#pragma unroll
        for (int nf=0;nf<4;nf++){
            int g = nf>>1, hi = nf&1;
#pragma unroll
            for (int ci=0;ci<4;ci++){
                int row = m0 + wm + mf*16 + (lane>>2) + (ci>>1)*8;
                int col = n0 + wn + g*16 + hi*8 + (lane&3)*2 + (ci&1);
                __half v = __float2half(acc[mf][nf][ci]);
                if (col < HH) g_Lh[(size_t)row*HF + col]      = v;
                else          g_Rh[(size_t)row*HF + col - HH] = v;
            }
        }
}

// ---------------- build_pairs: materialize A[pb][144][512] = L[i]*R[j] ----------------
__global__ __launch_bounds__(256) void build_pairs(){
    __shared__ __half Ls[4*HF];       // 256 uint4
    __shared__ __half Rs[36*HF];      // 2304 uint4
    const int pb = blockIdx.x, tid = threadIdx.x;
    const int b = pb/9, ig = pb - b*9;
    const int lrow0 = b*NR + ig*4, rbase = b*NR;
    {
        const uint4* lsrc = reinterpret_cast<const uint4*>(g_Lh + (size_t)lrow0*HF);
        reinterpret_cast<uint4*>(Ls)[tid] = lsrc[tid];
        const uint4* rsrc = reinterpret_cast<const uint4*>(g_Rh + (size_t)rbase*HF);
        uint4* rd = reinterpret_cast<uint4*>(Rs);
#pragma unroll
        for (int q=0;q<9;q++){
            int i = tid + 256*q;
            rd[i] = rsrc[i];
        }
    }
    __syncthreads();
    uint4* dst = reinterpret_cast<uint4*>(g_A + (size_t)pb*144*HF);
    const uint4* L4 = reinterpret_cast<const uint4*>(Ls);
    const uint4* R4 = reinterpret_cast<const uint4*>(Rs);
#pragma unroll
    for (int v=0; v<36; v++){
        int idx = tid + 256*v;            // 0..9215
        int row = idx>>6, kv = idx&63;
        int gg = row/36, j = row - 36*gg;
        uint4 lv = L4[gg*64 + kv];
        uint4 rv = R4[j*64 + kv];
        __half2 a0 = __hmul2(*reinterpret_cast<__half2*>(&lv.x), *reinterpret_cast<__half2*>(&rv.x));
        __half2 a1 = __hmul2(*reinterpret_cast<__half2*>(&lv.y), *reinterpret_cast<__half2*>(&rv.y));
        __half2 a2 = __hmul2(*reinterpret_cast<__half2*>(&lv.z), *reinterpret_cast<__half2*>(&rv.z));
        __half2 a3 = __hmul2(*reinterpret_cast<__half2*>(&lv.w), *reinterpret_cast<__half2*>(&rv.w));
        uint4 ov;
        ov.x = *reinterpret_cast<uint32_t*>(&a0);
        ov.y = *reinterpret_cast<uint32_t*>(&a1);
        ov.z = *reinterpret_cast<uint32_t*>(&a2);
        ov.w = *reinterpret_cast<uint32_t*>(&a3);
        dst[idx] = ov;
    }
}

// ---------------- pair GEMM: BM=144, BN=256, 12 warps (3m x 4n, warp 48x64), 1 CTA/SM ----------------
#define PSM_A  0            // 3 x 11520 = 34560
#define PSM_B  34560        // 3 x 20480 = 61440
#define PSM_CS 96000        // 160 floats
#define PSM_TOT 96640

__device__ __forceinline__ void p_issue(uint32_t smb, int t, int buf, int tid, int n0, int pb){
    uint32_t Ab = smb + PSM_A + buf*11520;
    const char* asrc = (const char*)g_A + (size_t)pb*(144*HF*2) + (size_t)t*64;
    {   // A: 144 rows x 4 segs = 576 vecs
        int p = tid;
        cpa16(Ab + (p>>2)*80 + (p&3)*16, asrc + (size_t)(p>>2)*1024 + (p&3)*16);
        if (tid < 192){
            int p2 = tid + 384;
            cpa16(Ab + (p2>>2)*80 + (p2&3)*16, asrc + (size_t)(p2>>2)*1024 + (p2&3)*16);
        }
    }
    uint32_t Bb = smb + PSM_B + buf*20480;
    const char* bsrc = (const char*)g_Wt + (size_t)n0*1024 + (size_t)t*64;
    {   // B: 256 rows x 4 segs = 1024 vecs
        int p = tid;
        cpa16(Bb + (p>>2)*80 + (p&3)*16, bsrc + (size_t)(p>>2)*1024 + (p&3)*16);
#pragma unroll
        for (int q=1;q<3;q++){
            int p2 = tid + 384*q;
            if (p2 < 1024)
                cpa16(Bb + (p2>>2)*80 + (p2&3)*16, bsrc + (size_t)(p2>>2)*1024 + (p2&3)*16);
        }
    }
    cpa_commit();
}

__global__ void __launch_bounds__(384,1) pair_gemm(const float* __restrict__ mm,
                                                   const float* __restrict__ coords,
                                                   float* __restrict__ out){
    extern __shared__ char sm[];
    const int tid = threadIdx.x, w = tid>>5, lane = tid&31;
    const int n0 = blockIdx.x*256;
    const int pb = blockIdx.y, b = pb/9, ig = pb - b*9;
    const int lrow0 = b*NR + ig*4, rbase = b*NR;
    const uint32_t smb = sm_u32(sm);
    const int mrow0 = (w % 3)*48, ncol0 = (w / 3)*64;

    {
        float* cs = reinterpret_cast<float*>(sm + PSM_CS);
        if (tid < 16) cs[tid] = coords[(lrow0 + (tid>>2))*CC + (tid&3)];
        else if (tid < 160){ int e = tid-16; cs[tid] = coords[(rbase + (e>>2))*CC + (e&3)]; }
    }

    float acc[3][8][4];
#pragma unroll
    for (int m=0;m<3;m++) for (int n=0;n<8;n++) for (int c=0;c<4;c++) acc[m][n][c]=0.f;

    p_issue(smb, 0, 0, tid, n0, pb);
    p_issue(smb, 1, 1, tid, n0, pb);

    for (int t=0; t<16; t++){
        if (t < 15) cpa_wait1(); else cpa_wait0();
        __syncthreads();
        if (t < 14) p_issue(smb, t+2, (t+2)%3, tid, n0, pb);

        const uint32_t ab = smb + PSM_A + (t%3)*11520;
        const uint32_t bb = smb + PSM_B + (t%3)*20480;
#pragma unroll
        for (int ks=0; ks<2; ks++){
            uint32_t a[3][4];
#pragma unroll
            for (int mf=0;mf<3;mf++)
                ldm_x4(a[mf], ab + (uint32_t)(mrow0 + mf*16 + (lane&15))*80 + ks*32 + ((lane>>4)<<4));
            uint32_t bf[4][4];
#pragma unroll
            for (int g=0; g<4; g++)
                ldm_x4(bf[g], bb + (uint32_t)(ncol0 + g*16 + (lane&15))*80 + ks*32 + ((lane>>4)<<4));
#pragma unroll
            for (int mf=0;mf<3;mf++)
#pragma unroll
                for (int nf=0;nf<8;nf++){
                    int g = nf>>1, hi = nf&1;
                    mma16816(acc[mf][nf], a[mf], bf[g][hi], bf[g][hi+2]);
                }
        }
    }
    __syncthreads();

    // ---- coord chunk (K=16): A = outer(c_i,c_j)/64, B = T tile (256 rows) ----
    {
        {   // B: 256 rows x 2 segs = 512 vecs
            int p = tid;
            if (p < 384) cpa16(smb + PSM_B + (p>>1)*80 + (p&1)*16,
                               (const char*)g_T + (size_t)(n0+(p>>1))*32 + (p&1)*16);
            int p2 = tid + 384;
            if (p2 < 512) cpa16(smb + PSM_B + (p2>>1)*80 + (p2&1)*16,
                                (const char*)g_T + (size_t)(n0+(p2>>1))*32 + (p2&1)*16);
        }
        cpa_commit();
        if (tid < 144){
            const float* cs = reinterpret_cast<const float*>(sm + PSM_CS);
            int gg = tid/36, j = tid - gg*36;
            float ci[4], cj[4];
#pragma unroll
            for (int p=0;p<4;p++){ ci[p] = cs[gg*4+p]; cj[p] = cs[16 + j*4 + p]; }
            char* Ab = sm + PSM_A;
#pragma unroll
            for (int e2=0;e2<8;e2++){
                int p0 = (e2*2)>>2, q0 = (e2*2)&3, p1 = (e2*2+1)>>2, q1 = (e2*2+1)&3;
                *reinterpret_cast<__half2*>(Ab + tid*80 + e2*4) =
                    __floats2half2_rn(ci[p0]*cj[q0]*0.015625f, ci[p1]*cj[q1]*0.015625f);
            }
        }
        cpa_wait0();
        __syncthreads();
        uint32_t a[3][4], bf[4][4];
#pragma unroll
        for (int mf=0;mf<3;mf++)
            ldm_x4(a[mf], smb + PSM_A + (uint32_t)(mrow0 + mf*16 + (lane&15))*80 + ((lane>>4)<<4));
#pragma unroll
        for (int g=0; g<4; g++)
            ldm_x4(bf[g], smb + PSM_B + (uint32_t)(ncol0 + g*16 + (lane&15))*80 + ((lane>>4)<<4));
#pragma unroll
        for (int mf=0;mf<3;mf++)
#pragma unroll
            for (int nf=0;nf<8;nf++){
                int g = nf>>1, hi = nf&1;
                mma16816(acc[mf][nf], a[mf], bf[g][hi], bf[g][hi+2]);
            }
    }
    __syncthreads();

    // epilogue: register-merge same-group rows, then smem atomicMax (4 groups x 256 cols)
    unsigned* redu = reinterpret_cast<unsigned*>(sm);
#pragma unroll
    for (int q=0;q<3;q++){
        int idx = tid + 384*q;
        if (idx < 1024) redu[idx] = 0u;
    }
    __syncthreads();
    int ggs[6];
#pragma unroll
    for (int s=0;s<6;s++){
        int row = mrow0 + (s>>1)*16 + (s&1)*8 + (lane>>2);
        ggs[s] = row/36;
    }
#pragma unroll
    for (int nf=0;nf<8;nf++)
#pragma unroll
        for (int cj=0;cj<2;cj++){
            int col = ncol0 + nf*8 + (lane&3)*2 + cj;
            float v = acc[0][nf][cj];
            int g0 = ggs[0];
#pragma unroll
            for (int s=1;s<6;s++){
                float nv = acc[s>>1][nf][(s&1)*2+cj];
                if (ggs[s] == g0) v = fmaxf(v, nv);
                else { atomicMax(&redu[g0*256 + col], f2mono(v)); g0 = ggs[s]; v = nv; }
            }
            atomicMax(&redu[g0*256 + col], f2mono(v));
        }
    __syncthreads();
#pragma unroll
    for (int q=0;q<3;q++){
        int idx = tid + 384*q;
        if (idx < 1024){
            int gg = idx>>8, col = idx&255;
            float v = mono2f(redu[idx]);
            size_t o = (size_t)(lrow0 + gg)*DD + n0 + col;
            out[o] = v + mm[o];
        }
    }
}

// ---------------- launch ----------------
extern "C" void kernel_launch(void* const* d_in, const int* in_sizes, int n_in,
                              void* d_out, int out_size){
    (void)in_sizes; (void)n_in; (void)out_size;
    const float* mm     = (const float*)d_in[0];
    const float* coords = (const float*)d_in[1];
    const float* W_cl   = (const float*)d_in[2];
    const float* W_cr   = (const float*)d_in[3];
    const float* W_cout = (const float*)d_in[4];
    const float* W_fl   = (const float*)d_in[5];
    const float* W_fr   = (const float*)d_in[6];
    const float* W_fout = (const float*)d_in[7];
    float* out = (float*)d_out;

    cudaFuncSetAttribute(pair_gemm, cudaFuncAttributeMaxDynamicSharedMemorySize, PSM_TOT);

    prep_all    <<<2816, 256>>>(mm, W_fout, W_fl, W_fr, W_cl, W_cr, W_cout);
    prep_T_final<<<128, 256>>>();
    stage1_gemm <<<dim3(8,18), 256>>>();
    build_pairs <<<288, 256>>>();
    pair_gemm   <<<dim3(8,288), 384, PSM_TOT>>>(mm, coords, out);
}